// round 16
// baseline (speedup 1.0000x reference)
#include <cuda_runtime.h>
#include <cuda_bf16.h>
#include <math.h>

// ---------------- problem constants ----------------
#define BB     32
#define CC     128
#define HH     64
#define WW_    64
#define WS     8
#define SHIFT  4
#define HEADS  4
#define DH     32
#define HID    512
#define METAH  256
#define TOK    64
#define NW     64
#define BW     2048
#define BTOK   131072
#define HW     4096

#define GEMM_DSMEM 56064

// ---------------- scratch ----------------
static __device__ __align__(16) float g_buf0[BTOK * CC];      // attn out
static __device__ __align__(16) float g_qkv [BTOK * 3 * CC];  // q-hat | k-hat | v (tf32-rounded, pre-scaled)
static __device__ __align__(16) float g_ffn1[BTOK * HID];
static __device__ __align__(16) float g_om  [BTOK * CC];      // proj out / ffn2 out
static __device__ __align__(16) float g_skip[BTOK * CC];      // LN1 residual
static __device__ __align__(16) float g_bias[HEADS * TOK * TOK];
static __device__ __align__(16) unsigned g_wtf[49152 + 16384 + 65536 + 65536];
#define WOFF_QKV  0
#define WOFF_PROJ 49152
#define WOFF_FFN1 65536
#define WOFF_FFN2 131072

// ---------------- helpers ----------------
__device__ __forceinline__ float warp_sum(float v) {
    #pragma unroll
    for (int o = 16; o > 0; o >>= 1) v += __shfl_xor_sync(0xffffffffu, v, o);
    return v;
}
__device__ __forceinline__ float quad_sum(float v) {
    v += __shfl_xor_sync(0xffffffffu, v, 1);
    v += __shfl_xor_sync(0xffffffffu, v, 2);
    return v;
}
__device__ __forceinline__ float quad_max(float v) {
    v = fmaxf(v, __shfl_xor_sync(0xffffffffu, v, 1));
    v = fmaxf(v, __shfl_xor_sync(0xffffffffu, v, 2));
    return v;
}
__device__ __forceinline__ float gelu_exact(float x) {
    return 0.5f * x * (1.0f + erff(x * 0.70710678118654752440f));
}
__device__ __forceinline__ unsigned f2tf32(float f) {
    unsigned r;
    asm("cvt.rna.tf32.f32 %0, %1;" : "=r"(r) : "f"(f));
    return r;
}
__device__ __forceinline__ float tf32r(float f) {
    return __uint_as_float(f2tf32(f));
}
__device__ __forceinline__ void mma_tf32(float& c0, float& c1, float& c2, float& c3,
                                         unsigned a0, unsigned a1, unsigned a2, unsigned a3,
                                         unsigned b0, unsigned b1) {
    asm volatile(
        "mma.sync.aligned.m16n8k8.row.col.f32.tf32.tf32.f32 "
        "{%0,%1,%2,%3}, {%4,%5,%6,%7}, {%8,%9}, {%0,%1,%2,%3};\n"
        : "+f"(c0), "+f"(c1), "+f"(c2), "+f"(c3)
        : "r"(a0), "r"(a1), "r"(a2), "r"(a3), "r"(b0), "r"(b1));
}
__device__ __forceinline__ void cp_async16(void* smem_ptr, const void* gmem_ptr) {
    unsigned sa = (unsigned)__cvta_generic_to_shared(smem_ptr);
    asm volatile("cp.async.ca.shared.global [%0], [%1], 16;" :: "r"(sa), "l"(gmem_ptr));
}
__device__ __forceinline__ void cp_commit() {
    asm volatile("cp.async.commit_group;");
}
template <int N>
__device__ __forceinline__ void cp_wait() {
    asm volatile("cp.async.wait_group %0;" :: "n"(N));
}

// ---------------- combined weight prep ----------------
__global__ void prep_all_kernel(const float* __restrict__ qkv_w,
                                const float* __restrict__ proj_w,
                                const float* __restrict__ fw1,
                                const float* __restrict__ fw2) {
    int idx = blockIdx.x * 256 + threadIdx.x;
    const float* w; int N, K, off, local;
    if (idx < 49152)       { w = qkv_w;  N = 384; K = 128; off = WOFF_QKV;  local = idx; }
    else if (idx < 65536)  { w = proj_w; N = 128; K = 128; off = WOFF_PROJ; local = idx - 49152; }
    else if (idx < 131072) { w = fw1;    N = 512; K = 128; off = WOFF_FFN1; local = idx - 65536; }
    else                   { w = fw2;    N = 128; K = 512; off = WOFF_FFN2; local = idx - 131072; }
    int nt  = local / (K * 128);
    int rem = local - nt * K * 128;
    int k = rem >> 7;
    int n = rem & 127;
    int pn = (n & 7) * 16 + (n >> 3);
    g_wtf[off + nt * K * 128 + k * 128 + pn] = f2tf32(w[k * N + nt * 128 + n]);
}

// ---------------- meta MLP relative-position bias table ----------------
__global__ void meta_kernel(const float* __restrict__ w1, const float* __restrict__ b1,
                            const float* __restrict__ w2, const float* __restrict__ b2) {
    int pq = blockIdx.x * 256 + threadIdx.x;
    int p = pq >> 6, q = pq & 63;
    float d0 = (float)((p >> 3) - (q >> 3));
    float d1 = (float)((p & 7) - (q & 7));
    float r0 = (d0 > 0.f ? 1.f : (d0 < 0.f ? -1.f : 0.f)) * log1pf(fabsf(d0));
    float r1 = (d1 > 0.f ? 1.f : (d1 < 0.f ? -1.f : 0.f)) * log1pf(fabsf(d1));
    float acc0 = 0.f, acc1 = 0.f, acc2 = 0.f, acc3 = 0.f;
    for (int j = 0; j < METAH; j++) {
        float hv = fmaxf(r0 * w1[j] + r1 * w1[METAH + j] + b1[j], 0.f);
        acc0 += hv * w2[j * 4 + 0];
        acc1 += hv * w2[j * 4 + 1];
        acc2 += hv * w2[j * 4 + 2];
        acc3 += hv * w2[j * 4 + 3];
    }
    g_bias[0 * 4096 + pq] = acc0 + b2[0];
    g_bias[1 * 4096 + pq] = acc1 + b2[1];
    g_bias[2 * 4096 + pq] = acc2 + b2[2];
    g_bias[3 * 4096 + pq] = acc3 + b2[3];
}

// ---------------- 3-stage cp.async tf32 GEMM, A from row-major buffer ----------------
template <int ACT, int N, int K>
__device__ __forceinline__ void gemm_tc_body(const float* __restrict__ A,
                                             const unsigned* __restrict__ Wt,
                                             const float* __restrict__ bias,
                                             float* __restrict__ C) {
    extern __shared__ char dynsmem[];
    float    (*As)[128][20]  = reinterpret_cast<float(*)[128][20]>(dynsmem);
    unsigned (*Bs)[16][132]  = reinterpret_cast<unsigned(*)[16][132]>(dynsmem + 3 * 128 * 20 * 4);

    const int tid  = threadIdx.x;
    const int warp = tid >> 5, lane = tid & 31;
    const int gid  = lane >> 2, tig = lane & 3;
    const int wm   = (warp & 3) * 32;
    const int wn   = (warp >> 2) * 64;
    const int m0   = blockIdx.y * 128, n0tile = blockIdx.x;

    const unsigned* wsrc = Wt + (size_t)n0tile * K * 128;

    const int akq = (tid & 3) << 2;
    const float* arow[2];
    #pragma unroll
    for (int it = 0; it < 2; it++) {
        int m = (tid >> 2) + it * 64;
        arow[it] = A + (size_t)(m0 + m) * K;
    }
    const int bkk = tid >> 5;
    const int bnq = (tid & 31) << 2;

    float c[2][8][4];
    #pragma unroll
    for (int mt = 0; mt < 2; mt++)
        #pragma unroll
        for (int nt = 0; nt < 8; nt++)
            #pragma unroll
            for (int r = 0; r < 4; r++) c[mt][nt][r] = 0.f;

    const int bfrag = gid * 16 + (warp >> 2) * 8;
    const int ar0 = wm + gid;

    constexpr int NT = K / 16;

    auto issue_tile = [&](int t) {
        int buf = t % 3;
        int k0 = t * 16;
        #pragma unroll
        for (int it = 0; it < 2; it++) {
            int m = (tid >> 2) + it * 64;
            cp_async16(&As[buf][m][akq], arow[it] + k0 + akq);
        }
        #pragma unroll
        for (int it = 0; it < 2; it++)
            cp_async16(&Bs[buf][bkk + it * 8][bnq],
                       wsrc + (size_t)(k0 + bkk + it * 8) * 128 + bnq);
    };

    issue_tile(0); cp_commit();
    issue_tile(1); cp_commit();

    #pragma unroll 1
    for (int t = 0; t < NT; t++) {
        cp_wait<1>();
        __syncthreads();
        if (t + 2 < NT) issue_tile(t + 2);
        cp_commit();

        const int cur = t % 3;
        #pragma unroll
        for (int ks = 0; ks < 16; ks += 8) {
            unsigned a0[4], a1[4];
            a0[0] = f2tf32(As[cur][ar0     ][ks + tig]);
            a0[1] = f2tf32(As[cur][ar0 +  8][ks + tig]);
            a0[2] = f2tf32(As[cur][ar0     ][ks + tig + 4]);
            a0[3] = f2tf32(As[cur][ar0 +  8][ks + tig + 4]);
            a1[0] = f2tf32(As[cur][ar0 + 16][ks + tig]);
            a1[1] = f2tf32(As[cur][ar0 + 24][ks + tig]);
            a1[2] = f2tf32(As[cur][ar0 + 16][ks + tig + 4]);
            a1[3] = f2tf32(As[cur][ar0 + 24][ks + tig + 4]);
            uint4 b0lo = *(const uint4*)&Bs[cur][ks + tig    ][bfrag];
            uint4 b1lo = *(const uint4*)&Bs[cur][ks + tig    ][bfrag + 4];
            uint4 b0hi = *(const uint4*)&Bs[cur][ks + tig + 4][bfrag];
            uint4 b1hi = *(const uint4*)&Bs[cur][ks + tig + 4][bfrag + 4];

            unsigned blo[8] = {b0lo.x, b0lo.y, b0lo.z, b0lo.w,
                               b1lo.x, b1lo.y, b1lo.z, b1lo.w};
            unsigned bhi[8] = {b0hi.x, b0hi.y, b0hi.z, b0hi.w,
                               b1hi.x, b1hi.y, b1hi.z, b1hi.w};

            #pragma unroll
            for (int nt = 0; nt < 8; nt++) {
                mma_tf32(c[0][nt][0], c[0][nt][1], c[0][nt][2], c[0][nt][3],
                         a0[0], a0[1], a0[2], a0[3], blo[nt], bhi[nt]);
                mma_tf32(c[1][nt][0], c[1][nt][1], c[1][nt][2], c[1][nt][3],
                         a1[0], a1[1], a1[2], a1[3], blo[nt], bhi[nt]);
            }
        }
    }

    #pragma unroll
    for (int mt = 0; mt < 2; mt++) {
        int row0 = m0 + wm + mt * 16 + gid;
        #pragma unroll
        for (int nt = 0; nt < 8; nt++) {
            int col = n0tile * 128 + wn + nt * 8 + tig * 2;
            float b0 = bias[col], b1 = bias[col + 1];
            float v0 = c[mt][nt][0] + b0;
            float v1 = c[mt][nt][1] + b1;
            float v2 = c[mt][nt][2] + b0;
            float v3 = c[mt][nt][3] + b1;
            if (ACT == 1) {
                v0 = gelu_exact(v0); v1 = gelu_exact(v1);
                v2 = gelu_exact(v2); v3 = gelu_exact(v3);
            }
            float2 p0; p0.x = v0; p0.y = v1;
            float2 p1; p1.x = v2; p1.y = v3;
            *(float2*)(C + (size_t)row0 * N + col) = p0;
            *(float2*)(C + (size_t)(row0 + 8) * N + col) = p1;
        }
    }
}

// ---------------- QKV GEMM: A gathered directly from x; epilogue normalizes q,k ----------------
__global__ __launch_bounds__(256, 2) void gemm_qkv_kernel(const float* __restrict__ x,
                                                          const float* __restrict__ bias,
                                                          const float* __restrict__ tau) {
    extern __shared__ char dynsmem[];
    float    (*As)[16][136]  = reinterpret_cast<float(*)[16][136]>(dynsmem);
    unsigned (*Bs)[16][132]  = reinterpret_cast<unsigned(*)[16][132]>(dynsmem + 3 * 16 * 136 * 4);

    const int tid  = threadIdx.x;
    const int warp = tid >> 5, lane = tid & 31;
    const int gid  = lane >> 2, tig = lane & 3;
    const int wm   = (warp & 3) * 32;
    const int wn   = (warp >> 2) * 64;
    const int m0   = blockIdx.y * 128, n0tile = blockIdx.x;
    const int N = 384, K = 128;

    const unsigned* wsrc = g_wtf + WOFF_QKV + (size_t)n0tile * K * 128;

    const float* achunk[2];
    int akrow[2], amcol[2];
    #pragma unroll
    for (int it = 0; it < 2; it++) {
        int id = tid + it * 256;
        int k = id >> 5;
        int mc = id & 31;
        int r = m0 + mc * 4;
        int b = r >> 12;
        int widx = (r >> 6) & 63;
        int t = r & 63;
        int h = (((widx >> 3) << 3) + (t >> 3) + SHIFT) & 63;
        int w0 = (((widx & 7) << 3) + (t & 7) + SHIFT) & 63;
        achunk[it] = x + ((size_t)(b * CC + k) * HW) + h * 64 + w0;
        akrow[it] = k;
        amcol[it] = mc * 4;
    }
    const int bkk = tid >> 5;
    const int bnq = (tid & 31) << 2;

    float c[2][8][4];
    #pragma unroll
    for (int mt = 0; mt < 2; mt++)
        #pragma unroll
        for (int nt = 0; nt < 8; nt++)
            #pragma unroll
            for (int r = 0; r < 4; r++) c[mt][nt][r] = 0.f;

    const int bfrag = gid * 16 + (warp >> 2) * 8;
    const int ar0 = wm + gid;

    const int NT = K / 16;

    auto issue_tile = [&](int t) {
        int buf = t % 3;
        size_t koff = (size_t)t * 16 * HW;
        #pragma unroll
        for (int it = 0; it < 2; it++)
            cp_async16(&As[buf][akrow[it]][amcol[it]], achunk[it] + koff);
        int k0 = t * 16;
        #pragma unroll
        for (int it = 0; it < 2; it++)
            cp_async16(&Bs[buf][bkk + it * 8][bnq],
                       wsrc + (size_t)(k0 + bkk + it * 8) * 128 + bnq);
    };

    issue_tile(0); cp_commit();
    issue_tile(1); cp_commit();

    #pragma unroll 1
    for (int t = 0; t < NT; t++) {
        cp_wait<1>();
        __syncthreads();
        if (t + 2 < NT) issue_tile(t + 2);
        cp_commit();

        const int cur = t % 3;
        #pragma unroll
        for (int ks = 0; ks < 16; ks += 8) {
            unsigned a0[4], a1[4];
            a0[0] = f2tf32(As[cur][ks + tig    ][ar0]);
            a0[1] = f2tf32(As[cur][ks + tig    ][ar0 + 8]);
            a0[2] = f2tf32(As[cur][ks + tig + 4][ar0]);
            a0[3] = f2tf32(As[cur][ks + tig + 4][ar0 + 8]);
            a1[0] = f2tf32(As[cur][ks + tig    ][ar0 + 16]);
            a1[1] = f2tf32(As[cur][ks + tig    ][ar0 + 24]);
            a1[2] = f2tf32(As[cur][ks + tig + 4][ar0 + 16]);
            a1[3] = f2tf32(As[cur][ks + tig + 4][ar0 + 24]);
            uint4 b0lo = *(const uint4*)&Bs[cur][ks + tig    ][bfrag];
            uint4 b1lo = *(const uint4*)&Bs[cur][ks + tig    ][bfrag + 4];
            uint4 b0hi = *(const uint4*)&Bs[cur][ks + tig + 4][bfrag];
            uint4 b1hi = *(const uint4*)&Bs[cur][ks + tig + 4][bfrag + 4];

            unsigned blo[8] = {b0lo.x, b0lo.y, b0lo.z, b0lo.w,
                               b1lo.x, b1lo.y, b1lo.z, b1lo.w};
            unsigned bhi[8] = {b0hi.x, b0hi.y, b0hi.z, b0hi.w,
                               b1hi.x, b1hi.y, b1hi.z, b1hi.w};

            #pragma unroll
            for (int nt = 0; nt < 8; nt++) {
                mma_tf32(c[0][nt][0], c[0][nt][1], c[0][nt][2], c[0][nt][3],
                         a0[0], a0[1], a0[2], a0[3], blo[nt], bhi[nt]);
                mma_tf32(c[1][nt][0], c[1][nt][1], c[1][nt][2], c[1][nt][3],
                         a1[0], a1[1], a1[2], a1[3], blo[nt], bhi[nt]);
            }
        }
    }

    // ---- epilogue: bias, per-head normalize (q,k tiles), round, store ----
    #pragma unroll
    for (int mt = 0; mt < 2; mt++)
        #pragma unroll
        for (int nt = 0; nt < 8; nt++) {
            int col = n0tile * 128 + wn + nt * 8 + tig * 2;
            float b0 = bias[col], b1 = bias[col + 1];
            c[mt][nt][0] += b0; c[mt][nt][1] += b1;
            c[mt][nt][2] += b0; c[mt][nt][3] += b1;
        }
    if (n0tile < 2) {
        float it0 = 1.0f / fmaxf(tau[(wn >> 5)], 0.01f);
        float it1 = 1.0f / fmaxf(tau[(wn >> 5) + 1], 0.01f);
        #pragma unroll
        for (int mt = 0; mt < 2; mt++)
            #pragma unroll
            for (int h = 0; h < 2; h++)
                #pragma unroll
                for (int gph = 0; gph < 2; gph++) {
                    float s = 0.f;
                    #pragma unroll
                    for (int nt = gph * 4; nt < gph * 4 + 4; nt++) {
                        float v0 = c[mt][nt][2 * h], v1 = c[mt][nt][2 * h + 1];
                        s += v0 * v0 + v1 * v1;
                    }
                    s = quad_sum(s);
                    float sc = 1.0f / fmaxf(sqrtf(s), 1e-3f);
                    if (n0tile == 0) sc *= (gph == 0 ? it0 : it1);
                    #pragma unroll
                    for (int nt = gph * 4; nt < gph * 4 + 4; nt++) {
                        c[mt][nt][2 * h]     *= sc;
                        c[mt][nt][2 * h + 1] *= sc;
                    }
                }
    }
    #pragma unroll
    for (int mt = 0; mt < 2; mt++) {
        int row0 = m0 + wm + mt * 16 + gid;
        #pragma unroll
        for (int nt = 0; nt < 8; nt++) {
            int col = n0tile * 128 + wn + nt * 8 + tig * 2;
            float2 p0; p0.x = tf32r(c[mt][nt][0]); p0.y = tf32r(c[mt][nt][1]);
            float2 p1; p1.x = tf32r(c[mt][nt][2]); p1.y = tf32r(c[mt][nt][3]);
            *(float2*)(g_qkv + (size_t)row0 * N + col) = p0;
            *(float2*)(g_qkv + (size_t)(row0 + 8) * N + col) = p1;
        }
    }
}

__global__ __launch_bounds__(256, 2) void gemm_proj_kernel(const float* __restrict__ b) {
    gemm_tc_body<0, 128, 128>(g_buf0, g_wtf + WOFF_PROJ, b, g_om);
}
__global__ __launch_bounds__(256, 2) void gemm_ffn1_kernel(const float* __restrict__ b) {
    gemm_tc_body<1, 512, 128>(g_skip, g_wtf + WOFF_FFN1, b, g_ffn1);
}
__global__ __launch_bounds__(256, 2) void gemm_ffn2_kernel(const float* __restrict__ b) {
    gemm_tc_body<0, 128, 512>(g_ffn1, g_wtf + WOFF_FFN2, b, g_om);
}

// ---------------- tensor-core attention per (head, window) ----------------
// S aliases qs+ks (dead after S-phase mma). Softmax phase uses float4 smem ops:
// 12 vector ops/thread vs 48 scalar (the measured L1 bottleneck).
__global__ __launch_bounds__(256, 4) void attn_kernel() {
    const int head = blockIdx.x;
    const int bw = blockIdx.y;
    __shared__ __align__(16) char smem_raw[64 * 36 * 4 * 2];   // qs+ks / S union
    __shared__ __align__(16) unsigned vs[64][40];
    __shared__ float inv_s[64];
    __shared__ int cnt[64];
    unsigned (*qs)[36] = reinterpret_cast<unsigned(*)[36]>(smem_raw);
    unsigned (*ks)[36] = reinterpret_cast<unsigned(*)[36]>(smem_raw + 64 * 36 * 4);
    float    (*S)[68]  = reinterpret_cast<float(*)[68]>(smem_raw);   // alias

    const int tid = threadIdx.x;
    const int warp = tid >> 5, lane = tid & 31;
    const int gid = lane >> 2, tig = lane & 3;
    const int row = tid >> 2, part = tid & 3;

    {
        int ds = part << 3;
        const float* rp = g_qkv + (size_t)(bw * 64 + row) * 384 + head * 32 + ds;
        cp_async16(&qs[row][ds],     rp);
        cp_async16(&qs[row][ds + 4], rp + 4);
        cp_async16(&ks[row][ds],     rp + 128);
        cp_async16(&ks[row][ds + 4], rp + 132);
        cp_async16(&vs[row][ds],     rp + 256);
        cp_async16(&vs[row][ds + 4], rp + 260);
        cp_commit();
    }
    if (tid < 64) {
        int widx = bw & 63;
        int gh = (widx >> 3) * 8 + (tid >> 3);
        int gw = (widx & 7) * 8 + (tid & 7);
        int rh = gh < 56 ? 0 : (gh < 60 ? 1 : 2);
        int rw = gw < 56 ? 0 : (gw < 60 ? 1 : 2);
        cnt[tid] = rh * 3 + rw;
    }
    cp_wait<0>();
    __syncthreads();

    // ---- S = q-hat . k-hat^T  (results held in regs; S written after barrier) ----
    float sc[4][4];
    int sm0, sn0;
    {
        sm0 = (warp & 3) << 4;
        sn0 = (warp >> 2) << 5;
        float c[4][4];
        #pragma unroll
        for (int nt = 0; nt < 4; nt++)
            #pragma unroll
            for (int r = 0; r < 4; r++) c[nt][r] = 0.f;

        #pragma unroll
        for (int kk = 0; kk < 32; kk += 8) {
            unsigned a0 = qs[sm0 + gid    ][kk + tig];
            unsigned a1 = qs[sm0 + gid + 8][kk + tig];
            unsigned a2 = qs[sm0 + gid    ][kk + tig + 4];
            unsigned a3 = qs[sm0 + gid + 8][kk + tig + 4];
            #pragma unroll
            for (int nt = 0; nt < 4; nt++) {
                unsigned b0 = ks[sn0 + nt * 8 + gid][kk + tig];
                unsigned b1 = ks[sn0 + nt * 8 + gid][kk + tig + 4];
                mma_tf32(c[nt][0], c[nt][1], c[nt][2], c[nt][3],
                         a0, a1, a2, a3, b0, b1);
            }
        }
        const float* bp = g_bias + (head << 12);
        int i0 = sm0 + gid;
        int ci = cnt[i0], ci8 = cnt[i0 + 8];
        #pragma unroll
        for (int nt = 0; nt < 4; nt++) {
            int j = sn0 + nt * 8 + tig * 2;
            int cj0 = cnt[j], cj1 = cnt[j + 1];
            float2 bA = *(const float2*)&bp[i0 * 64 + j];
            float2 bB = *(const float2*)&bp[(i0 + 8) * 64 + j];
            sc[nt][0] = c[nt][0] + bA.x; if (ci  != cj0) sc[nt][0] -= 100.0f;
            sc[nt][1] = c[nt][1] + bA.y; if (ci  != cj1) sc[nt][1] -= 100.0f;
            sc[nt][2] = c[nt][2] + bB.x; if (ci8 != cj0) sc[nt][2] -= 100.0f;
            sc[nt][3] = c[nt][3] + bB.y; if (ci8 != cj1) sc[nt][3] -= 100.0f;
        }
    }
    __syncthreads();   // qs/ks reads complete -> safe to overwrite via S alias
    {
        int i0 = sm0 + gid;
        #pragma unroll
        for (int nt = 0; nt < 4; nt++) {
            int j = sn0 + nt * 8 + tig * 2;
            S[i0][j] = sc[nt][0]; S[i0][j + 1] = sc[nt][1];
            S[i0 + 8][j] = sc[nt][2]; S[i0 + 8][j + 1] = sc[nt][3];
        }
    }
    __syncthreads();

    // ---- softmax: float4 passes (max, then exp+store); row sums saved ----
    {
        int j0 = part << 4;
        float* sp = &S[row][j0];
        float m;
        {
            float4 v0 = *(const float4*)(sp);
            float4 v1 = *(const float4*)(sp + 4);
            float4 v2 = *(const float4*)(sp + 8);
            float4 v3 = *(const float4*)(sp + 12);
            m = fmaxf(fmaxf(fmaxf(v0.x, v0.y), fmaxf(v0.z, v0.w)),
                      fmaxf(fmaxf(v1.x, v1.y), fmaxf(v1.z, v1.w)));
            m = fmaxf(m, fmaxf(fmaxf(v2.x, v2.y), fmaxf(v2.z, v2.w)));
            m = fmaxf(m, fmaxf(fmaxf(v3.x, v3.y), fmaxf(v3.z, v3.w)));
        }
        m = quad_max(m);
        float s = 0.f;
        #pragma unroll
        for (int q = 0; q < 4; q++) {
            float4 v = *(const float4*)(sp + q * 4);
            float e0 = expf(v.x - m);
            float e1 = expf(v.y - m);
            float e2 = expf(v.z - m);
            float e3 = expf(v.w - m);
            s += e0 + e1 + e2 + e3;
            float4 o;
            o.x = __uint_as_float(f2tf32(e0));
            o.y = __uint_as_float(f2tf32(e1));
            o.z = __uint_as_float(f2tf32(e2));
            o.w = __uint_as_float(f2tf32(e3));
            *(float4*)(sp + q * 4) = o;
        }
        s = quad_sum(s);
        if (part == 0) inv_s[row] = 1.0f / s;
    }
    __syncthreads();

    // ---- O = P . V ----
    {
        const int m0 = (warp & 3) << 4;
        const int d0 = (warp >> 2) << 4;
        float c[2][4];
        #pragma unroll
        for (int nt = 0; nt < 2; nt++)
            #pragma unroll
            for (int r = 0; r < 4; r++) c[nt][r] = 0.f;

        #pragma unroll
        for (int kk = 0; kk < 64; kk += 8) {
            unsigned a0 = __float_as_uint(S[m0 + gid    ][kk + tig]);
            unsigned a1 = __float_as_uint(S[m0 + gid + 8][kk + tig]);
            unsigned a2 = __float_as_uint(S[m0 + gid    ][kk + tig + 4]);
            unsigned a3 = __float_as_uint(S[m0 + gid + 8][kk + tig + 4]);
            #pragma unroll
            for (int nt = 0; nt < 2; nt++) {
                unsigned b0 = vs[kk + tig    ][d0 + nt * 8 + gid];
                unsigned b1 = vs[kk + tig + 4][d0 + nt * 8 + gid];
                mma_tf32(c[nt][0], c[nt][1], c[nt][2], c[nt][3],
                         a0, a1, a2, a3, b0, b1);
            }
        }
        int i0 = m0 + gid;
        float iv0 = inv_s[i0], iv8 = inv_s[i0 + 8];
        #pragma unroll
        for (int nt = 0; nt < 2; nt++) {
            int d = d0 + nt * 8 + tig * 2;
            float* op = g_buf0 + (size_t)(bw * 64 + i0) * 128 + head * 32 + d;
            float2 r0; r0.x = c[nt][0] * iv0; r0.y = c[nt][1] * iv0;
            float2 r1; r1.x = c[nt][2] * iv8; r1.y = c[nt][3] * iv8;
            *(float2*)op = r0;
            *(float2*)(op + 8 * 128) = r1;
        }
    }
}

// ---------------- fold + roll-back + LN1 + residual (x read via smem transpose) ----------------
__global__ __launch_bounds__(256) void merge_ln1_kernel(const float* __restrict__ x,
                                                        const float* __restrict__ g,
                                                        const float* __restrict__ b) {
    __shared__ float xt[128][9];
    int r0 = blockIdx.x * 8;
    int bb = r0 >> 12;
    int hw0 = r0 & 4095;
    int tid = threadIdx.x;
    {
        int c = tid >> 1;
        int j = (tid & 1) * 4;
        float4 v = *(const float4*)(x + ((size_t)(bb * CC + c)) * HW + hw0 + j);
        xt[c][j + 0] = v.x; xt[c][j + 1] = v.y;
        xt[c][j + 2] = v.z; xt[c][j + 3] = v.w;
    }
    __syncthreads();
    int warp = tid >> 5, lane = tid & 31;
    int r = r0 + warp;
    int hw = r & 4095;
    int h = hw >> 6, w = hw & 63;
    int hs = (h - SHIFT) & 63, ws = (w - SHIFT) & 63;
    int omrow = (bb * 64 + (hs >> 3) * 8 + (ws >> 3)) * 64 + (hs & 7) * 8 + (ws & 7);
    const float* omp = g_om + (size_t)omrow * 128;
    float ov[4];
    float s = 0.f;
    #pragma unroll
    for (int i = 0; i < 4; i++) {
        ov[i] = omp[lane + 32 * i];
        s += ov[i];
    }
    s = warp_sum(s);
    float mu = s * (1.0f / 128.0f);
    float s2 = 0.f;
    #pragma unroll
    for (int i = 0; i < 4; i++) {
        float d = ov[i] - mu;
        s2 += d * d;
    }
    s2 = warp_sum(s2);
    float rstd = rsqrtf(s2 * (1.0f / 128.0f) + 1e-5f);
    float* skp = g_skip + (size_t)r * 128;
    #pragma unroll
    for (int i = 0; i < 4; i++) {
        int c = lane + 32 * i;
        skp[c] = xt[c][warp] + (ov[i] - mu) * rstd * g[c] + b[c];
    }
}

// ---------------- fused LN2 + residual + transpose-out ----------------
__global__ __launch_bounds__(256) void ln2_tr_kernel(const float* __restrict__ g,
                                                     const float* __restrict__ b,
                                                     float* __restrict__ out) {
    __shared__ float tile[32][132];
    int bb  = blockIdx.y;
    int hw0 = blockIdx.x * 32;
    int warp = threadIdx.x >> 5, lane = threadIdx.x & 31;
    float4 gg = ((const float4*)g)[lane];
    float4 bv = ((const float4*)b)[lane];
    #pragma unroll
    for (int rr = 0; rr < 4; rr++) {
        int rl = warp * 4 + rr;
        size_t rbase = ((size_t)bb * HW + hw0 + rl) * 32;
        float4 v = ((const float4*)g_om)[rbase + lane];
        float s = v.x + v.y + v.z + v.w;
        s = warp_sum(s);
        float mu = s * (1.0f / 128.0f);
        float dx = v.x - mu, dy = v.y - mu, dz = v.z - mu, dw = v.w - mu;
        float s2 = dx * dx + dy * dy + dz * dz + dw * dw;
        s2 = warp_sum(s2);
        float rstd = rsqrtf(s2 * (1.0f / 128.0f) + 1e-5f);
        float4 rr4 = ((const float4*)g_skip)[rbase + lane];
        float4 o;
        o.x = rr4.x + dx * rstd * gg.x + bv.x;
        o.y = rr4.y + dy * rstd * gg.y + bv.y;
        o.z = rr4.z + dz * rstd * gg.z + bv.z;
        o.w = rr4.w + dw * rstd * gg.w + bv.w;
        *(float4*)&tile[rl][lane * 4] = o;
    }
    __syncthreads();
    #pragma unroll
    for (int c = warp; c < 128; c += 8)
        out[(size_t)bb * CC * HW + (size_t)c * HW + hw0 + lane] = tile[lane][c];
}

// ---------------- launch ----------------
extern "C" void kernel_launch(void* const* d_in, const int* in_sizes, int n_in,
                              void* d_out, int out_size) {
    const float* x      = (const float*)d_in[0];
    const float* qkv_w  = (const float*)d_in[1];
    const float* qkv_b  = (const float*)d_in[2];
    const float* proj_w = (const float*)d_in[3];
    const float* proj_b = (const float*)d_in[4];
    const float* mw1    = (const float*)d_in[5];
    const float* mb1    = (const float*)d_in[6];
    const float* mw2    = (const float*)d_in[7];
    const float* mb2    = (const float*)d_in[8];
    const float* tau    = (const float*)d_in[9];
    const float* ln1g   = (const float*)d_in[10];
    const float* ln1b   = (const float*)d_in[11];
    const float* ln2g   = (const float*)d_in[12];
    const float* ln2b   = (const float*)d_in[13];
    const float* fw1    = (const float*)d_in[14];
    const float* fb1    = (const float*)d_in[15];
    const float* fw2    = (const float*)d_in[16];
    const float* fb2    = (const float*)d_in[17];
    float* out = (float*)d_out;

    cudaFuncSetAttribute(gemm_qkv_kernel,  cudaFuncAttributeMaxDynamicSharedMemorySize, GEMM_DSMEM);
    cudaFuncSetAttribute(gemm_proj_kernel, cudaFuncAttributeMaxDynamicSharedMemorySize, GEMM_DSMEM);
    cudaFuncSetAttribute(gemm_ffn1_kernel, cudaFuncAttributeMaxDynamicSharedMemorySize, GEMM_DSMEM);
    cudaFuncSetAttribute(gemm_ffn2_kernel, cudaFuncAttributeMaxDynamicSharedMemorySize, GEMM_DSMEM);

    meta_kernel<<<16, 256>>>(mw1, mb1, mw2, mb2);
    prep_all_kernel<<<768, 256>>>(qkv_w, proj_w, fw1, fw2);

    gemm_qkv_kernel<<<dim3(3, BTOK / 128), 256, GEMM_DSMEM>>>(x, qkv_b, tau);

    attn_kernel<<<dim3(HEADS, BW), 256>>>();

    gemm_proj_kernel<<<dim3(1, BTOK / 128), 256, GEMM_DSMEM>>>(proj_b);

    merge_ln1_kernel<<<BTOK / 8, 256>>>(x, ln1g, ln1b);

    gemm_ffn1_kernel<<<dim3(4, BTOK / 128), 256, GEMM_DSMEM>>>(fb1);
    gemm_ffn2_kernel<<<dim3(1, BTOK / 128), 256, GEMM_DSMEM>>>(fb2);

    ln2_tr_kernel<<<dim3(HW / 32, BB), 256>>>(ln2g, ln2b, out);
}